// round 9
// baseline (speedup 1.0000x reference)
#include <cuda_runtime.h>
#include <cstdint>

#define IN_DIM  128
#define OUT_DIM 128
#define NHEADS  4
#define NEG_SLOPE 0.2f

#define N_MAX 50000
#define E_MAX 1600000
#define FULL 0xFFFFFFFFu

typedef unsigned long long u64;

// -------- device scratch (static: no allocation allowed) --------
__device__ float g_hq   [N_MAX * NHEADS];
__device__ float g_kact [N_MAX * NHEADS];
__device__ float g_qagg [N_MAX * NHEADS];
__device__ float g_hproj[(size_t)N_MAX * OUT_DIM];
__device__ int   g_cnt  [N_MAX];   // zeroed at load; re-zeroed inside scan1 each run
__device__ int   g_off  [N_MAX + 1];
__device__ int   g_pos  [N_MAX];
__device__ int   g_bsum [256];
__device__ int   g_csr_col[E_MAX];

// packed dual-fp32 FMA (B300 FFMA2 — only reachable via PTX f32x2)
__device__ __forceinline__ void ffma2(u64& d, u64 a, u64 b) {
    asm("fma.rn.f32x2 %0, %1, %2, %0;" : "+l"(d) : "l"(a), "l"(b));
}
__device__ __forceinline__ float2 unpack_f32x2(u64 v) {
    float2 p;
    asm("mov.b64 {%0, %1}, %2;" : "=f"(p.x), "=f"(p.y) : "l"(v));
    return p;
}

// ================= kernel 1: projections (FFMA2 mainloop) =============
#define NPB 16
__global__ __launch_bounds__(128) void proj_kernel(
    const float* __restrict__ x,
    const float* __restrict__ Wq, const float* __restrict__ Wk,
    const float* __restrict__ Wl, const float* __restrict__ bl, int N)
{
    __shared__ float xs[NPB * IN_DIM];
    const int t = threadIdx.x;
    const int base = blockIdx.x * NPB;
    const int nn = min(NPB, N - base);
    if (nn <= 0) return;

    {
        const float4* xg = (const float4*)(x + (size_t)base * IN_DIM);
        float4* xs4 = (float4*)xs;
        const int tot4 = nn * (IN_DIM / 4);
        for (int i = t; i < tot4; i += 128) xs4[i] = xg[i];
    }
    __syncthreads();

    // per-head q/k projections: t = n2*8 + h
    {
        const int n2 = t >> 3;
        const int h  = t & 7;
        if (n2 < nn) {
            const float* wrow = (h < 4) ? (Wq + h * IN_DIM) : (Wk + (h - 4) * IN_DIM);
            const float4* w4 = (const float4*)wrow;
            const float4* xr = (const float4*)(xs + n2 * IN_DIM);
            float d = 0.0f;
            #pragma unroll
            for (int k = 0; k < IN_DIM / 4; k++) {
                float4 w = w4[k]; float4 xv = xr[k];
                d += w.x * xv.x + w.y * xv.y + w.z * xv.z + w.w * xv.w;
            }
            const int node = base + n2;
            if (h < 4) g_hq[node * NHEADS + h] = d;
            else       g_kact[node * NHEADS + (h - 4)] = (d >= 0.0f) ? d : NEG_SLOPE * d;
        }
    }

    // big projection: packed f32x2 accumulators (even/odd partial sums)
    u64 accp[NPB];
    #pragma unroll
    for (int n = 0; n < NPB; n++) accp[n] = 0ull;

    const ulonglong2* wl2 = (const ulonglong2*)(Wl + (size_t)t * IN_DIM);
    #pragma unroll 4
    for (int k = 0; k < IN_DIM / 4; k++) {
        ulonglong2 w = wl2[k];
        #pragma unroll
        for (int n = 0; n < NPB; n++) {
            ulonglong2 xv = ((const ulonglong2*)(xs + n * IN_DIM))[k];
            ffma2(accp[n], w.x, xv.x);
            ffma2(accp[n], w.y, xv.y);
        }
    }
    const float b = bl[t];
    for (int n = 0; n < nn; n++) {
        float2 p = unpack_f32x2(accp[n]);
        g_hproj[(size_t)(base + n) * OUT_DIM + t] = p.x + p.y + b;
    }
}

// ================= kernel 2: histogram of rows =================
__global__ __launch_bounds__(256) void hist_kernel(const int* __restrict__ rows, int E) {
    int e = blockIdx.x * 256 + threadIdx.x;
    if (e < E) atomicAdd(&g_cnt[rows[e]], 1);
}

// ================= scan (3 stages) =================
__device__ __forceinline__ int warp_incl_scan(int v, int lane) {
    #pragma unroll
    for (int d = 1; d < 32; d <<= 1) {
        int t = __shfl_up_sync(FULL, v, d);
        if (lane >= d) v += t;
    }
    return v;
}

__global__ __launch_bounds__(256) void scan1_kernel(int N) {
    int i = blockIdx.x * 256 + threadIdx.x;
    int lane = threadIdx.x & 31, wid = threadIdx.x >> 5;
    int v = 0;
    if (i < N) { v = g_cnt[i]; g_cnt[i] = 0; }  // re-zero for next replay
    int s = warp_incl_scan(v, lane);
    __shared__ int wsum[8];
    if (lane == 31) wsum[wid] = s;
    __syncthreads();
    if (wid == 0) {
        int ws = (lane < 8) ? wsum[lane] : 0;
        #pragma unroll
        for (int d = 1; d < 8; d <<= 1) {
            int t = __shfl_up_sync(FULL, ws, d);
            if (lane >= d) ws += t;
        }
        if (lane < 8) wsum[lane] = ws;
    }
    __syncthreads();
    int excl = s - v + (wid > 0 ? wsum[wid - 1] : 0);
    if (i < N) g_off[i] = excl;
    if (threadIdx.x == 255) g_bsum[blockIdx.x] = excl + v;
}

__global__ __launch_bounds__(256) void scan2_kernel(int nb) {
    int i = threadIdx.x;
    int lane = i & 31, wid = i >> 5;
    int v = (i < nb) ? g_bsum[i] : 0;
    int s = warp_incl_scan(v, lane);
    __shared__ int wsum[8];
    if (lane == 31) wsum[wid] = s;
    __syncthreads();
    if (wid == 0) {
        int ws = (lane < 8) ? wsum[lane] : 0;
        #pragma unroll
        for (int d = 1; d < 8; d <<= 1) {
            int t = __shfl_up_sync(FULL, ws, d);
            if (lane >= d) ws += t;
        }
        if (lane < 8) wsum[lane] = ws;
    }
    __syncthreads();
    int excl = s - v + (wid > 0 ? wsum[wid - 1] : 0);
    if (i < nb) g_bsum[i] = excl;
}

__global__ __launch_bounds__(256) void scan3_kernel(int N, int E) {
    int i = blockIdx.x * 256 + threadIdx.x;
    if (i < N) {
        int o = g_off[i] + g_bsum[i >> 8];
        g_off[i] = o;
        g_pos[i] = o;
    }
    if (i == 0) g_off[N] = E;
}

// ================= kernel: scatter edges into CSR =================
__global__ __launch_bounds__(256) void scatter_kernel(
    const int* __restrict__ rows, const int* __restrict__ cols, int E)
{
    int e = blockIdx.x * 256 + threadIdx.x;
    if (e >= E) return;
    int r = rows[e];
    int p = atomicAdd(&g_pos[r], 1);
    g_csr_col[p] = cols[e];
}

// ================= kernel: q_agg via CSR (no atomics) =================
__global__ __launch_bounds__(256) void qagg_csr_kernel(int N) {
    int w = (blockIdx.x * 256 + threadIdx.x) >> 5;
    int lane = threadIdx.x & 31;
    if (w >= N) return;
    int beg = g_off[w], end = g_off[w + 1];
    float4 acc = {0.f, 0.f, 0.f, 0.f};
    for (int e = beg + lane; e < end; e += 32) {
        int c = __ldg(g_csr_col + e);
        float4 v = __ldg(((const float4*)g_hq) + c);
        acc.x += v.x; acc.y += v.y; acc.z += v.z; acc.w += v.w;
    }
    #pragma unroll
    for (int d = 16; d; d >>= 1) {
        acc.x += __shfl_xor_sync(FULL, acc.x, d);
        acc.y += __shfl_xor_sync(FULL, acc.y, d);
        acc.z += __shfl_xor_sync(FULL, acc.z, d);
        acc.w += __shfl_xor_sync(FULL, acc.w, d);
    }
    if (lane == 0) ((float4*)g_qagg)[w] = acc;
}

// ================= fused attention + aggregation (warp per node) ======
__device__ __forceinline__ void agg_strip(float4& acc, float a, int c, int lane, int cnt) {
    #pragma unroll 8
    for (int j = 0; j < 32; j++) {
        if (j >= cnt) break;
        float aj = __shfl_sync(FULL, a, j);
        int   cj = __shfl_sync(FULL, c, j);
        float4 v = __ldg(((const float4*)g_hproj) + (size_t)cj * (OUT_DIM / 4) + lane);
        acc.x = fmaf(aj, v.x, acc.x);
        acc.y = fmaf(aj, v.y, acc.y);
        acc.z = fmaf(aj, v.z, acc.z);
        acc.w = fmaf(aj, v.w, acc.w);
    }
}

__global__ __launch_bounds__(256) void attn_agg_kernel(float* __restrict__ out, int N) {
    int node = (blockIdx.x * 256 + threadIdx.x) >> 5;
    int lane = threadIdx.x & 31;
    if (node >= N) return;
    const int beg = g_off[node], end = g_off[node + 1];
    const int deg = end - beg;

    float4* outp = ((float4*)out) + (size_t)node * (OUT_DIM / 4) + lane;
    if (deg == 0) { float4 z = {0.f,0.f,0.f,0.f}; *outp = z; return; }

    const float4 ka = ((const float4*)g_kact)[node];
    float4 acc = {0.f, 0.f, 0.f, 0.f};

    // pass 1: per-head max
    float4 mx = {-3.4e38f, -3.4e38f, -3.4e38f, -3.4e38f};
    for (int e = beg + lane; e < end; e += 32) {
        int c = __ldg(g_csr_col + e);
        float4 q = __ldg(((const float4*)g_qagg) + c);
        mx.x = fmaxf(mx.x, ka.x * q.x);
        mx.y = fmaxf(mx.y, ka.y * q.y);
        mx.z = fmaxf(mx.z, ka.z * q.z);
        mx.w = fmaxf(mx.w, ka.w * q.w);
    }
    #pragma unroll
    for (int d = 16; d; d >>= 1) {
        mx.x = fmaxf(mx.x, __shfl_xor_sync(FULL, mx.x, d));
        mx.y = fmaxf(mx.y, __shfl_xor_sync(FULL, mx.y, d));
        mx.z = fmaxf(mx.z, __shfl_xor_sync(FULL, mx.z, d));
        mx.w = fmaxf(mx.w, __shfl_xor_sync(FULL, mx.w, d));
    }

    // pass 2: per-head sum of exp
    float4 sm = {0.f, 0.f, 0.f, 0.f};
    for (int e = beg + lane; e < end; e += 32) {
        int c = __ldg(g_csr_col + e);
        float4 q = __ldg(((const float4*)g_qagg) + c);
        sm.x += __expf(ka.x * q.x - mx.x);
        sm.y += __expf(ka.y * q.y - mx.y);
        sm.z += __expf(ka.z * q.z - mx.z);
        sm.w += __expf(ka.w * q.w - mx.w);
    }
    #pragma unroll
    for (int d = 16; d; d >>= 1) {
        sm.x += __shfl_xor_sync(FULL, sm.x, d);
        sm.y += __shfl_xor_sync(FULL, sm.y, d);
        sm.z += __shfl_xor_sync(FULL, sm.z, d);
        sm.w += __shfl_xor_sync(FULL, sm.w, d);
    }
    float4 inv;
    inv.x = 0.25f * __fdividef(1.0f, sm.x + 1e-8f);
    inv.y = 0.25f * __fdividef(1.0f, sm.y + 1e-8f);
    inv.z = 0.25f * __fdividef(1.0f, sm.z + 1e-8f);
    inv.w = 0.25f * __fdividef(1.0f, sm.w + 1e-8f);

    // pass 3: alpha per edge strip, broadcast + accumulate
    for (int base = beg; base < end; base += 32) {
        int e = base + lane;
        float a = 0.0f; int c = 0;
        if (e < end) {
            c = __ldg(g_csr_col + e);
            float4 q = __ldg(((const float4*)g_qagg) + c);
            a = __expf(ka.x * q.x - mx.x) * inv.x
              + __expf(ka.y * q.y - mx.y) * inv.y
              + __expf(ka.z * q.z - mx.z) * inv.z
              + __expf(ka.w * q.w - mx.w) * inv.w;
        }
        agg_strip(acc, a, c, lane, min(32, end - base));
    }

    // fused final leaky relu + single coalesced write
    acc.x = (acc.x >= 0.f) ? acc.x : NEG_SLOPE * acc.x;
    acc.y = (acc.y >= 0.f) ? acc.y : NEG_SLOPE * acc.y;
    acc.z = (acc.z >= 0.f) ? acc.z : NEG_SLOPE * acc.z;
    acc.w = (acc.w >= 0.f) ? acc.w : NEG_SLOPE * acc.w;
    *outp = acc;
}

// ================= launch =================
extern "C" void kernel_launch(void* const* d_in, const int* in_sizes, int n_in,
                              void* d_out, int out_size)
{
    const float* x  = (const float*)d_in[0];
    const int*   ei = (const int*)d_in[1];
    const float* Wq = (const float*)d_in[2];
    const float* Wk = (const float*)d_in[3];
    const float* Wl = (const float*)d_in[4];
    const float* bl = (const float*)d_in[5];
    float* out = (float*)d_out;

    const int N = in_sizes[0] / IN_DIM;
    const int E = in_sizes[1] / 2;
    const int* rows = ei;
    const int* cols = ei + E;
    const int nblocksN = (N + 255) / 256;

    proj_kernel<<<(N + NPB - 1) / NPB, 128>>>(x, Wq, Wk, Wl, bl, N);
    hist_kernel<<<(E + 255) / 256, 256>>>(rows, E);
    scan1_kernel<<<nblocksN, 256>>>(N);   // also re-zeros g_cnt for next replay
    scan2_kernel<<<1, 256>>>(nblocksN);
    scan3_kernel<<<nblocksN, 256>>>(N, E);
    scatter_kernel<<<(E + 255) / 256, 256>>>(rows, cols, E);
    qagg_csr_kernel<<<(N * 32 + 255) / 256, 256>>>(N);
    attn_agg_kernel<<<(N * 32 + 255) / 256, 256>>>(out, N);
}

// round 13
// speedup vs baseline: 1.0733x; 1.0733x over previous
#include <cuda_runtime.h>
#include <cstdint>

#define IN_DIM  128
#define OUT_DIM 128
#define NHEADS  4
#define NEG_SLOPE 0.2f

#define N_MAX 50000
#define E_MAX 1600000
#define FULL 0xFFFFFFFFu
#define HIST_BLOCKS 296   // ~25% of resident CTA slots; LTS-atomic-bound anyway

// -------- device scratch (static: no allocation allowed) --------
__device__ float g_hq   [N_MAX * NHEADS];
__device__ float g_kact [N_MAX * NHEADS];
__device__ float g_qagg [N_MAX * NHEADS];
__device__ float g_hproj[(size_t)N_MAX * OUT_DIM];
__device__ int   g_cnt  [N_MAX];   // zeroed at load; re-zeroed inside scan1 each run
__device__ int   g_off  [N_MAX + 1];
__device__ int   g_pos  [N_MAX];
__device__ int   g_bsum [256];
__device__ int   g_csr_col[E_MAX];

// ===== fused front kernel: hist (low bids, grid-stride) + projections =====
// hist blocks occupy SMs first and stay resident (long grid-stride loop) while
// proj blocks fill remaining slots -> concurrent execution in ONE launch.
#define NPB 16
__global__ __launch_bounds__(128) void proj_hist_kernel(
    const float* __restrict__ x,
    const float* __restrict__ Wq, const float* __restrict__ Wk,
    const float* __restrict__ Wl, const float* __restrict__ bl,
    const int* __restrict__ rows, int N, int E)
{
    const int t = threadIdx.x;

    if ((int)blockIdx.x < HIST_BLOCKS) {
        // ---------- histogram partition ----------
        int i = blockIdx.x * 128 + t;
        const int stride = HIST_BLOCKS * 128;
        for (; i < E; i += stride)
            atomicAdd(&g_cnt[__ldg(rows + i)], 1);
        return;
    }

    // ---------- projection partition (R2 proj, verbatim) ----------
    __shared__ float xs[NPB * IN_DIM];
    const int base = ((int)blockIdx.x - HIST_BLOCKS) * NPB;
    const int nn = min(NPB, N - base);
    if (nn <= 0) return;

    {
        const float4* xg = (const float4*)(x + (size_t)base * IN_DIM);
        float4* xs4 = (float4*)xs;
        const int tot4 = nn * (IN_DIM / 4);
        for (int i = t; i < tot4; i += 128) xs4[i] = xg[i];
    }
    __syncthreads();

    // per-head q/k projections: t = n2*8 + h
    {
        const int n2 = t >> 3;
        const int h  = t & 7;
        if (n2 < nn) {
            const float* wrow = (h < 4) ? (Wq + h * IN_DIM) : (Wk + (h - 4) * IN_DIM);
            const float4* w4 = (const float4*)wrow;
            const float4* xr = (const float4*)(xs + n2 * IN_DIM);
            float d = 0.0f;
            #pragma unroll
            for (int k = 0; k < IN_DIM / 4; k++) {
                float4 w = w4[k]; float4 xv = xr[k];
                d += w.x * xv.x + w.y * xv.y + w.z * xv.z + w.w * xv.w;
            }
            const int node = base + n2;
            if (h < 4) g_hq[node * NHEADS + h] = d;
            else       g_kact[node * NHEADS + (h - 4)] = (d >= 0.0f) ? d : NEG_SLOPE * d;
        }
    }

    float acc[NPB];
    #pragma unroll
    for (int n = 0; n < NPB; n++) acc[n] = 0.0f;

    const float4* wl4 = (const float4*)(Wl + (size_t)t * IN_DIM);
    #pragma unroll 4
    for (int k = 0; k < IN_DIM / 4; k++) {
        float4 w = wl4[k];
        #pragma unroll
        for (int n = 0; n < NPB; n++) {
            float4 xv = ((const float4*)(xs + n * IN_DIM))[k];
            acc[n] += w.x * xv.x + w.y * xv.y + w.z * xv.z + w.w * xv.w;
        }
    }
    const float b = bl[t];
    for (int n = 0; n < nn; n++)
        g_hproj[(size_t)(base + n) * OUT_DIM + t] = acc[n] + b;
}

// ================= scan (3 stages) =================
__device__ __forceinline__ int warp_incl_scan(int v, int lane) {
    #pragma unroll
    for (int d = 1; d < 32; d <<= 1) {
        int t = __shfl_up_sync(FULL, v, d);
        if (lane >= d) v += t;
    }
    return v;
}

__global__ __launch_bounds__(256) void scan1_kernel(int N) {
    int i = blockIdx.x * 256 + threadIdx.x;
    int lane = threadIdx.x & 31, wid = threadIdx.x >> 5;
    int v = 0;
    if (i < N) { v = g_cnt[i]; g_cnt[i] = 0; }  // re-zero for next replay
    int s = warp_incl_scan(v, lane);
    __shared__ int wsum[8];
    if (lane == 31) wsum[wid] = s;
    __syncthreads();
    if (wid == 0) {
        int ws = (lane < 8) ? wsum[lane] : 0;
        #pragma unroll
        for (int d = 1; d < 8; d <<= 1) {
            int t = __shfl_up_sync(FULL, ws, d);
            if (lane >= d) ws += t;
        }
        if (lane < 8) wsum[lane] = ws;
    }
    __syncthreads();
    int excl = s - v + (wid > 0 ? wsum[wid - 1] : 0);
    if (i < N) g_off[i] = excl;
    if (threadIdx.x == 255) g_bsum[blockIdx.x] = excl + v;
}

__global__ __launch_bounds__(256) void scan2_kernel(int nb) {
    int i = threadIdx.x;
    int lane = i & 31, wid = i >> 5;
    int v = (i < nb) ? g_bsum[i] : 0;
    int s = warp_incl_scan(v, lane);
    __shared__ int wsum[8];
    if (lane == 31) wsum[wid] = s;
    __syncthreads();
    if (wid == 0) {
        int ws = (lane < 8) ? wsum[lane] : 0;
        #pragma unroll
        for (int d = 1; d < 8; d <<= 1) {
            int t = __shfl_up_sync(FULL, ws, d);
            if (lane >= d) ws += t;
        }
        if (lane < 8) wsum[lane] = ws;
    }
    __syncthreads();
    int excl = s - v + (wid > 0 ? wsum[wid - 1] : 0);
    if (i < nb) g_bsum[i] = excl;
}

__global__ __launch_bounds__(256) void scan3_kernel(int N, int E) {
    int i = blockIdx.x * 256 + threadIdx.x;
    if (i < N) {
        int o = g_off[i] + g_bsum[i >> 8];
        g_off[i] = o;
        g_pos[i] = o;
    }
    if (i == 0) g_off[N] = E;
}

// ================= kernel: scatter edges into CSR =================
__global__ __launch_bounds__(256) void scatter_kernel(
    const int* __restrict__ rows, const int* __restrict__ cols, int E)
{
    int e = blockIdx.x * 256 + threadIdx.x;
    if (e >= E) return;
    int r = rows[e];
    int p = atomicAdd(&g_pos[r], 1);
    g_csr_col[p] = cols[e];
}

// ================= kernel: q_agg via CSR (no atomics) =================
__global__ __launch_bounds__(256) void qagg_csr_kernel(int N) {
    int w = (blockIdx.x * 256 + threadIdx.x) >> 5;
    int lane = threadIdx.x & 31;
    if (w >= N) return;
    int beg = g_off[w], end = g_off[w + 1];
    float4 acc = {0.f, 0.f, 0.f, 0.f};
    for (int e = beg + lane; e < end; e += 32) {
        int c = __ldg(g_csr_col + e);
        float4 v = __ldg(((const float4*)g_hq) + c);
        acc.x += v.x; acc.y += v.y; acc.z += v.z; acc.w += v.w;
    }
    #pragma unroll
    for (int d = 16; d; d >>= 1) {
        acc.x += __shfl_xor_sync(FULL, acc.x, d);
        acc.y += __shfl_xor_sync(FULL, acc.y, d);
        acc.z += __shfl_xor_sync(FULL, acc.z, d);
        acc.w += __shfl_xor_sync(FULL, acc.w, d);
    }
    if (lane == 0) ((float4*)g_qagg)[w] = acc;
}

// ================= fused attention + aggregation (warp per node) ======
__device__ __forceinline__ void agg_strip(float4& acc, float a, int c, int lane, int cnt) {
    #pragma unroll 8
    for (int j = 0; j < 32; j++) {
        if (j >= cnt) break;
        float aj = __shfl_sync(FULL, a, j);
        int   cj = __shfl_sync(FULL, c, j);
        float4 v = __ldg(((const float4*)g_hproj) + (size_t)cj * (OUT_DIM / 4) + lane);
        acc.x = fmaf(aj, v.x, acc.x);
        acc.y = fmaf(aj, v.y, acc.y);
        acc.z = fmaf(aj, v.z, acc.z);
        acc.w = fmaf(aj, v.w, acc.w);
    }
}

__global__ __launch_bounds__(256) void attn_agg_kernel(float* __restrict__ out, int N) {
    int node = (blockIdx.x * 256 + threadIdx.x) >> 5;
    int lane = threadIdx.x & 31;
    if (node >= N) return;
    const int beg = g_off[node], end = g_off[node + 1];
    const int deg = end - beg;

    float4* outp = ((float4*)out) + (size_t)node * (OUT_DIM / 4) + lane;
    if (deg == 0) { float4 z = {0.f,0.f,0.f,0.f}; *outp = z; return; }

    const float4 ka = ((const float4*)g_kact)[node];
    float4 acc = {0.f, 0.f, 0.f, 0.f};

    // pass 1: per-head max
    float4 mx = {-3.4e38f, -3.4e38f, -3.4e38f, -3.4e38f};
    for (int e = beg + lane; e < end; e += 32) {
        int c = __ldg(g_csr_col + e);
        float4 q = __ldg(((const float4*)g_qagg) + c);
        mx.x = fmaxf(mx.x, ka.x * q.x);
        mx.y = fmaxf(mx.y, ka.y * q.y);
        mx.z = fmaxf(mx.z, ka.z * q.z);
        mx.w = fmaxf(mx.w, ka.w * q.w);
    }
    #pragma unroll
    for (int d = 16; d; d >>= 1) {
        mx.x = fmaxf(mx.x, __shfl_xor_sync(FULL, mx.x, d));
        mx.y = fmaxf(mx.y, __shfl_xor_sync(FULL, mx.y, d));
        mx.z = fmaxf(mx.z, __shfl_xor_sync(FULL, mx.z, d));
        mx.w = fmaxf(mx.w, __shfl_xor_sync(FULL, mx.w, d));
    }

    // pass 2: per-head sum of exp
    float4 sm = {0.f, 0.f, 0.f, 0.f};
    for (int e = beg + lane; e < end; e += 32) {
        int c = __ldg(g_csr_col + e);
        float4 q = __ldg(((const float4*)g_qagg) + c);
        sm.x += __expf(ka.x * q.x - mx.x);
        sm.y += __expf(ka.y * q.y - mx.y);
        sm.z += __expf(ka.z * q.z - mx.z);
        sm.w += __expf(ka.w * q.w - mx.w);
    }
    #pragma unroll
    for (int d = 16; d; d >>= 1) {
        sm.x += __shfl_xor_sync(FULL, sm.x, d);
        sm.y += __shfl_xor_sync(FULL, sm.y, d);
        sm.z += __shfl_xor_sync(FULL, sm.z, d);
        sm.w += __shfl_xor_sync(FULL, sm.w, d);
    }
    float4 inv;
    inv.x = 0.25f * __fdividef(1.0f, sm.x + 1e-8f);
    inv.y = 0.25f * __fdividef(1.0f, sm.y + 1e-8f);
    inv.z = 0.25f * __fdividef(1.0f, sm.z + 1e-8f);
    inv.w = 0.25f * __fdividef(1.0f, sm.w + 1e-8f);

    // pass 3: alpha per edge strip, broadcast + accumulate
    for (int base = beg; base < end; base += 32) {
        int e = base + lane;
        float a = 0.0f; int c = 0;
        if (e < end) {
            c = __ldg(g_csr_col + e);
            float4 q = __ldg(((const float4*)g_qagg) + c);
            a = __expf(ka.x * q.x - mx.x) * inv.x
              + __expf(ka.y * q.y - mx.y) * inv.y
              + __expf(ka.z * q.z - mx.z) * inv.z
              + __expf(ka.w * q.w - mx.w) * inv.w;
        }
        agg_strip(acc, a, c, lane, min(32, end - base));
    }

    // fused final leaky relu + single coalesced write
    acc.x = (acc.x >= 0.f) ? acc.x : NEG_SLOPE * acc.x;
    acc.y = (acc.y >= 0.f) ? acc.y : NEG_SLOPE * acc.y;
    acc.z = (acc.z >= 0.f) ? acc.z : NEG_SLOPE * acc.z;
    acc.w = (acc.w >= 0.f) ? acc.w : NEG_SLOPE * acc.w;
    *outp = acc;
}

// ================= launch =================
extern "C" void kernel_launch(void* const* d_in, const int* in_sizes, int n_in,
                              void* d_out, int out_size)
{
    const float* x  = (const float*)d_in[0];
    const int*   ei = (const int*)d_in[1];
    const float* Wq = (const float*)d_in[2];
    const float* Wk = (const float*)d_in[3];
    const float* Wl = (const float*)d_in[4];
    const float* bl = (const float*)d_in[5];
    float* out = (float*)d_out;

    const int N = in_sizes[0] / IN_DIM;
    const int E = in_sizes[1] / 2;
    const int* rows = ei;
    const int* cols = ei + E;
    const int nblocksN = (N + 255) / 256;
    const int proj_blocks = (N + NPB - 1) / NPB;

    // 1: hist (resident low-bid partition) + projections, concurrent in one launch
    proj_hist_kernel<<<HIST_BLOCKS + proj_blocks, 128>>>(x, Wq, Wk, Wl, bl, rows, N, E);
    // 2-4: offsets (scan1 re-zeros g_cnt for next replay)
    scan1_kernel<<<nblocksN, 256>>>(N);
    scan2_kernel<<<1, 256>>>(nblocksN);
    scan3_kernel<<<nblocksN, 256>>>(N, E);
    // 5: scatter edges into CSR
    scatter_kernel<<<(E + 255) / 256, 256>>>(rows, cols, E);
    // 6: q aggregation (no atomics)
    qagg_csr_kernel<<<(N * 32 + 255) / 256, 256>>>(N);
    // 7: fused softmax + weighted aggregation + leaky
    attn_agg_kernel<<<(N * 32 + 255) / 256, 256>>>(out, N);
}